// round 15
// baseline (speedup 1.0000x reference)
#include <cuda_runtime.h>
#include <cuda_fp16.h>
#include <cstdint>
#include <math.h>

// Problem dims
#define Bb 32
#define Ss 512
#define Ee 300
#define Hh 512
#define Tt 9
#define G4 4096                 // 2 dirs * 4H
#define MROWS (Bb*Ss)           // 16384

// ---------------- scratch (device globals; no allocation allowed) ----------------
__device__ float g_xg [(size_t)MROWS * G4];     // GEMM output [m][n]
__device__ float g_xgT[(size_t)MROWS * G4];     // transposed  [(s*4096+n)*32+b]
__device__ float g_hT [(size_t)MROWS * 1024];   // scan output [(s*1024+k)*32+b]
__device__ float g_emis[(size_t)MROWS * Tt];
__device__ float g_part[Bb];
__device__ unsigned int g_cnt2[2 * 32];             // per-dir arrival counters (padded)
__device__ volatile unsigned int g_sense2[2 * 32];  // per-dir sense flags (padded)
// fp16 operand buffers
__device__ __half g_Af[(size_t)MROWS * 1024];
__device__ __half g_Wf[(size_t)G4 * 1024];
__device__ __half g_Whh[(size_t)2 * 2048 * 512];
__device__ __half g_hst[2 * 2 * Bb * Hh];       // fp16 h-state ring [buf][dir][b][k]

// ---------------- helpers ----------------
__device__ __forceinline__ uint32_t smem_u32(const void* p) {
    uint32_t a;
    asm("{ .reg .u64 t; cvta.to.shared.u64 t, %1; cvt.u32.u64 %0, t; }" : "=r"(a) : "l"(p));
    return a;
}
#define CP16(sm, gp) \
    asm volatile("cp.async.cg.shared.global [%0], [%1], 16;" :: "r"(sm), "l"(gp))
#define CP_COMMIT() asm volatile("cp.async.commit_group;" ::: "memory")
#define CP_WAIT1()  asm volatile("cp.async.wait_group 1;" ::: "memory")
#define CP_WAIT0()  asm volatile("cp.async.wait_group 0;" ::: "memory")
#define LDSM4(r, a) \
    asm volatile("ldmatrix.sync.aligned.m8n8.x4.shared.b16 {%0,%1,%2,%3}, [%4];" \
        : "=r"((r)[0]), "=r"((r)[1]), "=r"((r)[2]), "=r"((r)[3]) : "r"(a))
#define LDSM2(r, a) \
    asm volatile("ldmatrix.sync.aligned.m8n8.x2.shared.b16 {%0,%1}, [%2];" \
        : "=r"((r)[0]), "=r"((r)[1]) : "r"(a))
#define MMA_F16(c, a, b) \
    asm volatile("mma.sync.aligned.m16n8k16.row.col.f32.f16.f16.f32 " \
        "{%0,%1,%2,%3}, {%4,%5,%6,%7}, {%8,%9}, {%0,%1,%2,%3};" \
        : "+f"((c)[0]), "+f"((c)[1]), "+f"((c)[2]), "+f"((c)[3]) \
        : "r"((a)[0]), "r"((a)[1]), "r"((a)[2]), "r"((a)[3]), "r"((b)[0]), "r"((b)[1]))

__device__ __forceinline__ float tanh_fast(float x) {
    float r;
    asm("tanh.approx.f32 %0, %1;" : "=f"(r) : "f"(x));
    return r;
}
__device__ __forceinline__ float sigf(float x) { return 1.f / (1.f + __expf(-x)); }

// swizzled smem byte offset for (row, 16B-granule g); 64B rows
__device__ __forceinline__ uint32_t swz(int row, int g) {
    return (uint32_t)(row * 64 + ((g ^ ((row >> 1) & 3)) << 4));
}

// =============================================================================
// fp32 -> fp16 convert (with K padding).
// =============================================================================
__global__ __launch_bounds__(256) void conv_f16(const float* __restrict__ in,
                                                __half* __restrict__ out,
                                                int rows, int Kin, int Kp)
{
    int total = rows * Kp;
    for (int idx = blockIdx.x * 256 + threadIdx.x; idx < total; idx += gridDim.x * 256) {
        int r = idx / Kp, c = idx - r * Kp;
        float v = (c < Kin) ? in[(size_t)r * Kin + c] : 0.f;
        out[idx] = __float2half(v);
    }
}

// =============================================================================
// Transpose xg[m][n] (m = b*512+s) -> xgT[(s*4096+n)*32 + b].
// =============================================================================
__global__ __launch_bounds__(256) void transp_xg(const float* __restrict__ in,
                                                 float* __restrict__ out)
{
    __shared__ float ts[128 * 33];
    const int s = blockIdx.y, n0 = blockIdx.x * 128, t = threadIdx.x;
#pragma unroll
    for (int i = 0; i < 16; i++) {
        int e = i * 256 + t;
        int bb = e >> 7, nn = e & 127;
        ts[nn * 33 + bb] = in[((size_t)(bb * 512 + s)) * G4 + n0 + nn];
    }
    __syncthreads();
#pragma unroll
    for (int i = 0; i < 16; i++) {
        int f = i * 256 + t;
        int bb = f & 31, nn = f >> 5;
        out[((size_t)s * G4 + n0 + nn) * 32 + bb] = ts[nn * 33 + bb];
    }
}

// =============================================================================
// Transpose hT -> Af[(b*512+s)*1024 + k] fp16 (layer-1 A operand).
// =============================================================================
__global__ __launch_bounds__(256) void transp_hA(const float* __restrict__ hT,
                                                 __half* __restrict__ Af)
{
    __shared__ float ts[128 * 33];
    const int s = blockIdx.y, k0 = blockIdx.x * 128, t = threadIdx.x;
#pragma unroll
    for (int i = 0; i < 16; i++) {
        int e = i * 256 + t;
        int bb = e & 31, kk = e >> 5;
        ts[kk * 33 + bb] = hT[((size_t)s * 1024 + k0 + kk) * 32 + bb];
    }
    __syncthreads();
#pragma unroll
    for (int i = 0; i < 16; i++) {
        int f = i * 256 + t;
        int bb = f >> 7, kk = f & 127;
        Af[((size_t)(bb * 512 + s)) * 1024 + k0 + kk] = __float2half(ts[kk * 33 + bb]);
    }
}

// =============================================================================
// Input-projection GEMM via mma.sync (fp16, fp32 accum). Tile 128x128, BK=32.
// =============================================================================
#define GEMM_SMEM 32768

__global__ __launch_bounds__(256, 2) void gemm_mma(
    const __half* __restrict__ A, const __half* __restrict__ W,
    const float* __restrict__ bias, float* __restrict__ C, int Kp)
{
    extern __shared__ char dsm[];
    const uint32_t smb = smem_u32(dsm);

    const int tid  = threadIdx.x;
    const int wid  = tid >> 5, lane = tid & 31;
    const int wm   = wid >> 2;
    const int wn   = wid & 3;
    const int m0   = blockIdx.y * 128;
    const int n0   = blockIdx.x * 128;

    const int sub = lane >> 3, lr = lane & 7;
    uint32_t offA[4][2], offB[2][2];
#pragma unroll
    for (int mi = 0; mi < 4; mi++) {
        int mrow = wm * 64 + mi * 16 + (sub & 1) * 8 + lr;
#pragma unroll
        for (int ks = 0; ks < 2; ks++)
            offA[mi][ks] = swz(mrow, ks * 2 + (sub >> 1));
    }
#pragma unroll
    for (int p = 0; p < 2; p++) {
        int nrow = wn * 32 + (p * 2 + (sub >> 1)) * 8 + lr;
#pragma unroll
        for (int ks = 0; ks < 2; ks++)
            offB[p][ks] = swz(nrow, ks * 2 + (sub & 1));
    }

    const int crow = tid >> 1;
    const int cg0  = (tid & 1) * 2;
    const uint32_t s0 = swz(crow, cg0), s1 = swz(crow, cg0 + 1);

    float acc[4][4][4];
#pragma unroll
    for (int mi = 0; mi < 4; mi++)
#pragma unroll
        for (int ni = 0; ni < 4; ni++)
#pragma unroll
            for (int q = 0; q < 4; q++) acc[mi][ni][q] = 0.f;

    const int nch = Kp >> 5;

    {
        const size_t ga = (size_t)(m0 + crow) * Kp + cg0 * 8;
        const size_t gb = (size_t)(n0 + crow) * Kp + cg0 * 8;
        CP16(smb + s0,        A + ga); CP16(smb + s1,        A + ga + 8);
        CP16(smb + 8192 + s0, W + gb); CP16(smb + 8192 + s1, W + gb + 8);
        CP_COMMIT();
    }

    for (int ch = 0; ch < nch; ch++) {
        if (ch + 1 < nch) {
            const int k0 = (ch + 1) << 5;
            const size_t ga = (size_t)(m0 + crow) * Kp + k0 + cg0 * 8;
            const size_t gb = (size_t)(n0 + crow) * Kp + k0 + cg0 * 8;
            uint32_t sb = smb + ((ch + 1) & 1) * 16384;
            CP16(sb + s0,        A + ga); CP16(sb + s1,        A + ga + 8);
            CP16(sb + 8192 + s0, W + gb); CP16(sb + 8192 + s1, W + gb + 8);
            CP_COMMIT();
            CP_WAIT1();
        } else {
            CP_WAIT0();
        }
        __syncthreads();

        const uint32_t bA = smb + (ch & 1) * 16384;
        const uint32_t bW = bA + 8192;

#pragma unroll
        for (int ks = 0; ks < 2; ks++) {
            uint32_t ah[4][4], bh[2][4];
#pragma unroll
            for (int mi = 0; mi < 4; mi++) LDSM4(ah[mi], bA + offA[mi][ks]);
#pragma unroll
            for (int p = 0; p < 2; p++)    LDSM4(bh[p], bW + offB[p][ks]);
#pragma unroll
            for (int mi = 0; mi < 4; mi++)
#pragma unroll
                for (int ni = 0; ni < 4; ni++) {
                    uint32_t* bf = &bh[ni >> 1][(ni & 1) * 2];
                    MMA_F16(acc[mi][ni], ah[mi], bf);
                }
        }
        __syncthreads();
    }

#pragma unroll
    for (int mi = 0; mi < 4; mi++) {
        const int row = m0 + wm * 64 + mi * 16 + (lane >> 2);
#pragma unroll
        for (int ni = 0; ni < 4; ni++) {
            const int col = n0 + wn * 32 + ni * 8 + (lane & 3) * 2;
            float2 bv = *(const float2*)(bias + col);
            float2 o0, o1;
            o0.x = acc[mi][ni][0] + bv.x; o0.y = acc[mi][ni][1] + bv.y;
            o1.x = acc[mi][ni][2] + bv.x; o1.y = acc[mi][ni][3] + bv.y;
            *(float2*)(C + (size_t)row * G4 + col)       = o0;
            *(float2*)(C + (size_t)(row + 8) * G4 + col) = o1;
        }
    }
}

// =============================================================================
// LSTM scan with HMMA recurrence. 512 threads (16 warps), K split across 2
// warp groups. PER-DIRECTION grid barrier (64 arrivals each) with the hT
// store overlapped into the barrier-wait window.
// =============================================================================
#define SCAN_SMEM 65536

__global__ __launch_bounds__(512, 1) void lstm_scan_mma(
    const float* __restrict__ xgT, const __half* __restrict__ whh,
    const float* __restrict__ b_hh, float* __restrict__ hT)
{
    extern __shared__ char dsm[];
    const uint32_t wbase = smem_u32(dsm);          // W: 16 chunks x 2KB
    const uint32_t hbase = wbase + 32768;          // h: 16 chunks x 2KB
    __shared__ float g_s[2][32 * 33 + 16];

    const int tid  = threadIdx.x;
    const int wid  = tid >> 5, lane = tid & 31;
    const int dir  = blockIdx.x >> 6;
    const int blk  = blockIdx.x & 63;
    const int j0   = blk * 8;
    const bool cell = (tid < 256);
    const int b    = tid & 31;           // batch (cell update, tid<256)
    const int j    = tid >> 5;           // hidden unit 0..7 (tid<256)
    const int jg   = j0 + (cell ? j : 0);

    // warp tile: wm {0,1} batch 16-group, wn {0..3} col 8-group, kp {0,1} K half
    const int wm = wid & 1, wn = (wid >> 1) & 3, kp = wid >> 3;
    const int sub = lane >> 3, lr = lane & 7;
    uint32_t offA_h[2], offB_h[2];
#pragma unroll
    for (int kh = 0; kh < 2; kh++) {
        offA_h[kh] = swz(wm * 16 + (sub & 1) * 8 + lr, kh * 2 + (sub >> 1));
        offB_h[kh] = swz(wn * 8 + lr,                  kh * 2 + (sub & 1));
    }

    // ---- stage W_hh rows (32 rows x 512 k fp16) once ----
#pragma unroll
    for (int i = 0; i < 4; i++) {
        int gid = i * 512 + tid;
        int r  = gid >> 6;              // 0..31 = gate*8 + jl
        int kg = gid & 63;              // 16B granule (8 fp16)
        int grow = dir * 2048 + (r >> 3) * 512 + j0 + (r & 7);
        CP16(wbase + (kg >> 2) * 2048 + swz(r, kg & 3),
             whh + (size_t)grow * 512 + kg * 8);
    }
    CP_COMMIT();

    // ---- zero h smem (t=0 state) ----
#pragma unroll
    for (int i = 0; i < 4; i++) {
        int gid = i * 512 + tid;
        int r = gid >> 6, kg = gid & 63;
        *(uint4*)(dsm + 32768 + (kg >> 2) * 2048 + swz(r, kg & 3)) =
            make_uint4(0, 0, 0, 0);
    }
    CP_WAIT0();
    __syncthreads();

    const float bh0 = cell ? b_hh[dir * 2048 + 0 * 512 + jg] : 0.f;
    const float bh1 = cell ? b_hh[dir * 2048 + 1 * 512 + jg] : 0.f;
    const float bh2 = cell ? b_hh[dir * 2048 + 2 * 512 + jg] : 0.f;
    const float bh3 = cell ? b_hh[dir * 2048 + 3 * 512 + jg] : 0.f;

    unsigned int* const cnt   = &g_cnt2[dir * 32];
    volatile unsigned int* const sense = &g_sense2[dir * 32];

    float c = 0.f;
    unsigned ls = 0;

    for (int t = 0; t < Ss; t++) {
        const int s = dir ? (Ss - 1 - t) : t;

        // coalesced xgT reads (cell threads only)
        float x0 = 0.f, x1 = 0.f, x2 = 0.f, x3 = 0.f;
        if (cell) {
            const size_t xi = ((size_t)s * G4 + dir * 2048 + jg) * 32 + b;
            x0 = xgT[xi];
            x1 = xgT[xi + 512 * 32];
            x2 = xgT[xi + 1024 * 32];
            x3 = xgT[xi + 1536 * 32];
        }

        // stage h(t-1) fp16 (skip at t=0; smem already zero)
        if (t > 0) {
            const __half* hsrc = g_hst + (((t - 1) & 1) * 2 + dir) * (Bb * Hh);
#pragma unroll
            for (int i = 0; i < 4; i++) {
                int gid = i * 512 + tid;
                int bb = gid >> 6, kg = gid & 63;
                CP16(hbase + (kg >> 2) * 2048 + swz(bb, kg & 3),
                     hsrc + bb * 512 + kg * 8);
            }
            CP_COMMIT();
            CP_WAIT0();
        }
        __syncthreads();

        // MMA: each warp covers 8 K-chunks (half of K=512), 2 chains
        float ae[4] = {0.f, 0.f, 0.f, 0.f};
        float ao[4] = {0.f, 0.f, 0.f, 0.f};
        const uint32_t cb0 = kp * 8 * 2048;
#pragma unroll
        for (int ck = 0; ck < 8; ck++) {
            const uint32_t ab = hbase + cb0 + ck * 2048;
            const uint32_t bb = wbase + cb0 + ck * 2048;
            uint32_t a0[4], a1[4], b0[4], b1[4];
            LDSM4(a0, ab + offA_h[0]);
            LDSM2(b0, bb + offB_h[0]);
            LDSM4(a1, ab + offA_h[1]);
            LDSM2(b1, bb + offB_h[1]);
            MMA_F16(ae, a0, b0);
            MMA_F16(ao, a1, b1);
        }

        // partial gate preactivations -> smem slab kp
        {
            const int row = wm * 16 + (lane >> 2);
            const int col = wn * 8 + (lane & 3) * 2;
            g_s[kp][row * 33 + col]            = ae[0] + ao[0];
            g_s[kp][row * 33 + col + 1]        = ae[1] + ao[1];
            g_s[kp][(row + 8) * 33 + col]      = ae[2] + ao[2];
            g_s[kp][(row + 8) * 33 + col + 1]  = ae[3] + ao[3];
        }
        __syncthreads();

        // cell update for (b, jg) on first 256 threads
        float h = 0.f;
        if (cell) {
            float gi = g_s[0][b * 33 + j]      + g_s[1][b * 33 + j]      + x0 + bh0;
            float gf = g_s[0][b * 33 + 8 + j]  + g_s[1][b * 33 + 8 + j]  + x1 + bh1;
            float gc = g_s[0][b * 33 + 16 + j] + g_s[1][b * 33 + 16 + j] + x2 + bh2;
            float go = g_s[0][b * 33 + 24 + j] + g_s[1][b * 33 + 24 + j] + x3 + bh3;

            c = sigf(gf) * c + sigf(gi) * tanh_fast(gc);
            h = sigf(go) * tanh_fast(c);

            // publish h-state FIRST (this is what other blocks wait on)
            g_hst[((t & 1) * 2 + dir) * (Bb * Hh) + b * 512 + jg] = __float2half(h);
            __threadfence();
        }
        __syncthreads();

        // arrive at per-dir barrier, then overlap hT store with the wait
        ls ^= 1u;
        if (tid == 0) {
            unsigned prev = atomicAdd(cnt, 1u);
            if (prev == 63u) {
                atomicExch(cnt, 0u);
                __threadfence();
                *sense = ls;
            }
        }
        if (cell)
            hT[((size_t)s * 1024 + dir * 512 + jg) * 32 + b] = h;
        if (tid == 0) {
            while (*sense != ls) __nanosleep(32);
        }
        __syncthreads();
    }
}

// =============================================================================
// emissions from transposed h.
// =============================================================================
__global__ __launch_bounds__(256) void emis_t(const float* __restrict__ hT,
                                              const float* __restrict__ pw,
                                              const float* __restrict__ pb,
                                              float* __restrict__ em)
{
    __shared__ float red[9 * 8 * 32];
    const int s = blockIdx.x, t = threadIdx.x;
    const int kp = t >> 5, b = t & 31;

    float acc[9];
#pragma unroll
    for (int tt = 0; tt < 9; tt++) acc[tt] = 0.f;

    const float* hp = hT + ((size_t)s * 1024 + kp * 128) * 32 + b;
    const float* pwp = pw + kp * 128;
    for (int k = 0; k < 128; k++) {
        float hv = hp[(size_t)k * 32];
#pragma unroll
        for (int tt = 0; tt < 9; tt++) acc[tt] += hv * pwp[tt * 1024 + k];
    }
#pragma unroll
    for (int tt = 0; tt < 9; tt++) red[(tt * 8 + kp) * 32 + b] = acc[tt];
    __syncthreads();
    if (kp < 4) {
#pragma unroll
        for (int tt = 0; tt < 9; tt++)
            red[(tt * 8 + kp) * 32 + b] += red[(tt * 8 + kp + 4) * 32 + b];
    }
    __syncthreads();
    if (kp < 2) {
#pragma unroll
        for (int tt = 0; tt < 9; tt++)
            red[(tt * 8 + kp) * 32 + b] += red[(tt * 8 + kp + 2) * 32 + b];
    }
    __syncthreads();
    if (kp == 0) {
#pragma unroll
        for (int tt = 0; tt < 9; tt++)
            em[((size_t)(b * 512 + s)) * 9 + tt] =
                red[(tt * 8) * 32 + b] + red[(tt * 8 + 1) * 32 + b] + pb[tt];
    }
}

// =============================================================================
// CRF NLL per batch (warp per batch); target_tag arrives int32.
// =============================================================================
__global__ __launch_bounds__(32) void crf_kernel(const float* __restrict__ em,
                                                 const int* __restrict__ tags,
                                                 const int* __restrict__ mask,
                                                 const float* __restrict__ trans,
                                                 const float* __restrict__ st,
                                                 const float* __restrict__ en,
                                                 float* __restrict__ outp)
{
    const int b = blockIdx.x, lane = threadIdx.x;
    const float* eb = em + (size_t)b * Ss * Tt;
    const int* tb = tags + (size_t)b * Ss;
    const int* mb = mask + (size_t)b * Ss;

    float part = 0.f; int cnt = 0;
    for (int t = 1 + lane; t < Ss; t += 32) {
        float mf = (float)mb[t];
        int tg = tb[t], tp = tb[t - 1];
        part += (eb[t * Tt + tg] + trans[tp * Tt + tg]) * mf;
    }
    for (int t = lane; t < Ss; t += 32) cnt += (mb[t] != 0);
#pragma unroll
    for (int o = 16; o; o >>= 1) {
        part += __shfl_down_sync(0xffffffffu, part, o);
        cnt  += __shfl_down_sync(0xffffffffu, cnt, o);
    }
    cnt  = __shfl_sync(0xffffffffu, cnt, 0);
    part = __shfl_sync(0xffffffffu, part, 0);

    const int jj = lane;
    const bool act = (jj < Tt);
    float trl[9];
#pragma unroll
    for (int i = 0; i < 9; i++) trl[i] = act ? trans[i * Tt + jj] : 0.f;
    float alpha = act ? (st[jj] + eb[jj]) : -1e30f;

    for (int t = 1; t < Ss; t++) {
        float ai[9];
        float m = -1e30f;
#pragma unroll
        for (int i = 0; i < 9; i++) {
            ai[i] = __shfl_sync(0xffffffffu, alpha, i) + trl[i];
            m = fmaxf(m, ai[i]);
        }
        float ssum = 0.f;
#pragma unroll
        for (int i = 0; i < 9; i++) ssum += __expf(ai[i] - m);
        float nxt = m + __logf(ssum) + (act ? eb[t * Tt + jj] : 0.f);
        if (act && mb[t]) alpha = nxt;
    }

    float v = act ? (alpha + en[jj]) : -1e30f;
    float mm = v;
#pragma unroll
    for (int o = 16; o; o >>= 1) mm = fmaxf(mm, __shfl_xor_sync(0xffffffffu, mm, o));
    float ex = __expf(v - mm);
#pragma unroll
    for (int o = 16; o; o >>= 1) ex += __shfl_xor_sync(0xffffffffu, ex, o);
    float denom = mm + __logf(ex);

    if (lane == 0) {
        int t0 = tb[0];
        float num = st[t0] + eb[t0] + part + en[tb[cnt - 1]];
        outp[b] = num - denom;
    }
}

__global__ void final_kernel(const float* __restrict__ p, float* __restrict__ out)
{
    const int lane = threadIdx.x;
    float v = p[lane];
#pragma unroll
    for (int o = 16; o; o >>= 1) v += __shfl_down_sync(0xffffffffu, v, o);
    if (lane == 0) out[0] = -(v / 32.f);
}

// =============================================================================
// kernel_launch
// =============================================================================
extern "C" void kernel_launch(void* const* d_in, const int* in_sizes, int n_in,
                              void* d_out, int out_size)
{
    const float* we   = (const float*)d_in[0];
    const int*   tg   = (const int*)d_in[1];
    const int*   mk   = (const int*)d_in[2];
    const float* wih0 = (const float*)d_in[3];
    const float* whh0 = (const float*)d_in[4];
    const float* bih0 = (const float*)d_in[5];
    const float* bhh0 = (const float*)d_in[6];
    const float* wih1 = (const float*)d_in[7];
    const float* whh1 = (const float*)d_in[8];
    const float* bih1 = (const float*)d_in[9];
    const float* bhh1 = (const float*)d_in[10];
    const float* pw   = (const float*)d_in[11];
    const float* pb   = (const float*)d_in[12];
    const float* tr   = (const float*)d_in[13];
    const float* st   = (const float*)d_in[14];
    const float* en   = (const float*)d_in[15];

    float *xg, *xgT, *hT, *emis, *part;
    __half *Af, *Wf, *Whh;
    cudaGetSymbolAddress((void**)&xg,   g_xg);
    cudaGetSymbolAddress((void**)&xgT,  g_xgT);
    cudaGetSymbolAddress((void**)&hT,   g_hT);
    cudaGetSymbolAddress((void**)&emis, g_emis);
    cudaGetSymbolAddress((void**)&part, g_part);
    cudaGetSymbolAddress((void**)&Af,   g_Af);
    cudaGetSymbolAddress((void**)&Wf,   g_Wf);
    cudaGetSymbolAddress((void**)&Whh,  g_Whh);

    cudaFuncSetAttribute(lstm_scan_mma, cudaFuncAttributeMaxDynamicSharedMemorySize, SCAN_SMEM);
    cudaFuncSetAttribute(gemm_mma,      cudaFuncAttributeMaxDynamicSharedMemorySize, GEMM_SMEM);

    dim3 ggrid(32, 128);        // GEMM (N/128, M/128)
    dim3 tgrid(32, 512);        // xg transpose (n-tiles, s)
    dim3 hgrid(8, 512);         // h transpose (k-tiles, s)

    // ---- Layer 0 ----
    conv_f16<<<2048, 256>>>(we,   Af, MROWS, Ee, 320);
    conv_f16<<<512,  256>>>(wih0, Wf, G4,    Ee, 320);
    gemm_mma<<<ggrid, 256, GEMM_SMEM>>>(Af, Wf, bih0, xg, 320);
    transp_xg<<<tgrid, 256>>>(xg, xgT);
    conv_f16<<<1024, 256>>>(whh0, Whh, 4096, 512, 512);
    lstm_scan_mma<<<128, 512, SCAN_SMEM>>>(xgT, Whh, bhh0, hT);

    // ---- Layer 1 ----
    transp_hA<<<hgrid, 256>>>(hT, Af);
    conv_f16<<<1024, 256>>>(wih1, Wf, G4, 1024, 1024);
    gemm_mma<<<ggrid, 256, GEMM_SMEM>>>(Af, Wf, bih1, xg, 1024);
    transp_xg<<<tgrid, 256>>>(xg, xgT);
    conv_f16<<<1024, 256>>>(whh1, Whh, 4096, 512, 512);
    lstm_scan_mma<<<128, 512, SCAN_SMEM>>>(xgT, Whh, bhh1, hT);

    // ---- Emissions + CRF + final reduce ----
    emis_t<<<512, 256>>>(hT, pw, pb, emis);
    crf_kernel<<<32, 32>>>(emis, tg, mk, tr, st, en, part);
    final_kernel<<<1, 32>>>(part, (float*)d_out);
}

// round 16
// speedup vs baseline: 1.0814x; 1.0814x over previous
#include <cuda_runtime.h>
#include <cuda_fp16.h>
#include <cstdint>
#include <math.h>

// Problem dims
#define Bb 32
#define Ss 512
#define Ee 300
#define Hh 512
#define Tt 9
#define G4 4096                 // 2 dirs * 4H
#define MROWS (Bb*Ss)           // 16384

// ---------------- scratch (device globals; no allocation allowed) ----------------
__device__ float g_xgT[(size_t)MROWS * G4];     // GEMM out, transposed [(s*4096+n)*32+b]
__device__ __half g_hT [(size_t)MROWS * 1024];  // scan output [(s*1024+k)*32+b] fp16
__device__ float g_emis[(size_t)MROWS * Tt];
__device__ float g_part[Bb];
__device__ unsigned int g_bar_cnt = 0;
__device__ volatile unsigned int g_bar_sense = 0;
// fp16 operand buffers
__device__ __half g_Af[(size_t)MROWS * 1024];   // A operand, time-major rows (s*32+b)
__device__ __half g_Wf[(size_t)G4 * 1024];
__device__ __half g_Whh[(size_t)2 * 2048 * 512];
__device__ __half g_hst[2 * 2 * Bb * Hh];       // fp16 h-state ring [buf][dir][b][k]

// ---------------- helpers ----------------
__device__ __forceinline__ uint32_t smem_u32(const void* p) {
    uint32_t a;
    asm("{ .reg .u64 t; cvta.to.shared.u64 t, %1; cvt.u32.u64 %0, t; }" : "=r"(a) : "l"(p));
    return a;
}
#define CP16(sm, gp) \
    asm volatile("cp.async.cg.shared.global [%0], [%1], 16;" :: "r"(sm), "l"(gp))
#define CP_COMMIT() asm volatile("cp.async.commit_group;" ::: "memory")
#define CP_WAIT1()  asm volatile("cp.async.wait_group 1;" ::: "memory")
#define CP_WAIT0()  asm volatile("cp.async.wait_group 0;" ::: "memory")
#define LDSM4(r, a) \
    asm volatile("ldmatrix.sync.aligned.m8n8.x4.shared.b16 {%0,%1,%2,%3}, [%4];" \
        : "=r"((r)[0]), "=r"((r)[1]), "=r"((r)[2]), "=r"((r)[3]) : "r"(a))
#define LDSM2(r, a) \
    asm volatile("ldmatrix.sync.aligned.m8n8.x2.shared.b16 {%0,%1}, [%2];" \
        : "=r"((r)[0]), "=r"((r)[1]) : "r"(a))
#define MMA_F16(c, a, b) \
    asm volatile("mma.sync.aligned.m16n8k16.row.col.f32.f16.f16.f32 " \
        "{%0,%1,%2,%3}, {%4,%5,%6,%7}, {%8,%9}, {%0,%1,%2,%3};" \
        : "+f"((c)[0]), "+f"((c)[1]), "+f"((c)[2]), "+f"((c)[3]) \
        : "r"((a)[0]), "r"((a)[1]), "r"((a)[2]), "r"((a)[3]), "r"((b)[0]), "r"((b)[1]))

__device__ __forceinline__ float tanh_fast(float x) {
    float r;
    asm("tanh.approx.f32 %0, %1;" : "=f"(r) : "f"(x));
    return r;
}
__device__ __forceinline__ float sigf(float x) { return 1.f / (1.f + __expf(-x)); }

// swizzled smem byte offset for (row, 16B-granule g); 64B rows
__device__ __forceinline__ uint32_t swz(int row, int g) {
    return (uint32_t)(row * 64 + ((g ^ ((row >> 1) & 3)) << 4));
}

// =============================================================================
// fp32 -> fp16 convert (row-major preserved, K padded). For W operands.
// =============================================================================
__global__ __launch_bounds__(256) void conv_f16(const float* __restrict__ in,
                                                __half* __restrict__ out,
                                                int rows, int Kin, int Kp)
{
    int total = rows * Kp;
    for (int idx = blockIdx.x * 256 + threadIdx.x; idx < total; idx += gridDim.x * 256) {
        int r = idx / Kp, c = idx - r * Kp;
        float v = (c < Kin) ? in[(size_t)r * Kin + c] : 0.f;
        out[idx] = __float2half(v);
    }
}

// =============================================================================
// we (B,S,E) -> Af[(s*32+b)*320 + e] fp16 (row permutation + pad). grid = 512 s.
// =============================================================================
__global__ __launch_bounds__(256) void conv_weT(const float* __restrict__ we,
                                                __half* __restrict__ Af)
{
    const int s = blockIdx.x;
    for (int idx = threadIdx.x; idx < 32 * 320; idx += 256) {
        int b = idx / 320, e = idx - b * 320;
        float v = (e < Ee) ? we[((size_t)(b * 512 + s)) * Ee + e] : 0.f;
        Af[((size_t)(s * 32 + b)) * 320 + e] = __float2half(v);
    }
}

// =============================================================================
// hT fp16 [(s*1024+k)*32+b] -> Af[(s*32+b)*1024 + k] fp16 (layer-1 A operand).
// grid (8 k-tiles, 512 s), 256 threads.
// =============================================================================
__global__ __launch_bounds__(256) void transp_hA(const __half* __restrict__ hT,
                                                 __half* __restrict__ Af)
{
    __shared__ __half ts[128 * 33];
    const int s = blockIdx.y, k0 = blockIdx.x * 128, t = threadIdx.x;
#pragma unroll
    for (int i = 0; i < 16; i++) {
        int e = i * 256 + t;
        int bb = e & 31, kk = e >> 5;
        ts[kk * 33 + bb] = hT[((size_t)s * 1024 + k0 + kk) * 32 + bb];
    }
    __syncthreads();
#pragma unroll
    for (int i = 0; i < 16; i++) {
        int f = i * 256 + t;
        int bb = f >> 7, kk = f & 127;
        Af[((size_t)(s * 32 + bb)) * 1024 + k0 + kk] = ts[kk * 33 + bb];
    }
}

// =============================================================================
// GEMM via mma.sync (fp16, fp32 accum), A in time-major rows (s*32+b).
// Writes output DIRECTLY TRANSPOSED: xgT[(s*4096+n0+n)*32+b].
// Tile 128x128 (= 4 s x 32 b), BK=32, 256 thr. Epilogue: two 64-row passes
// staged through smem (64x129 fp32) for coalesced transposed stores.
// =============================================================================
#define GEMM_SMEM 33024   // max(mainloop 32KB, epilogue 64*129*4)

__global__ __launch_bounds__(256, 2) void gemm_mma(
    const __half* __restrict__ A, const __half* __restrict__ W,
    const float* __restrict__ bias, float* __restrict__ C, int Kp)
{
    extern __shared__ char dsm[];
    const uint32_t smb = smem_u32(dsm);

    const int tid  = threadIdx.x;
    const int wid  = tid >> 5, lane = tid & 31;
    const int wm   = wid >> 2;
    const int wn   = wid & 3;
    const int m0   = blockIdx.y * 128;
    const int n0   = blockIdx.x * 128;

    const int sub = lane >> 3, lr = lane & 7;
    uint32_t offA[4][2], offB[2][2];
#pragma unroll
    for (int mi = 0; mi < 4; mi++) {
        int mrow = wm * 64 + mi * 16 + (sub & 1) * 8 + lr;
#pragma unroll
        for (int ks = 0; ks < 2; ks++)
            offA[mi][ks] = swz(mrow, ks * 2 + (sub >> 1));
    }
#pragma unroll
    for (int p = 0; p < 2; p++) {
        int nrow = wn * 32 + (p * 2 + (sub >> 1)) * 8 + lr;
#pragma unroll
        for (int ks = 0; ks < 2; ks++)
            offB[p][ks] = swz(nrow, ks * 2 + (sub & 1));
    }

    const int crow = tid >> 1;
    const int cg0  = (tid & 1) * 2;
    const uint32_t s0 = swz(crow, cg0), s1 = swz(crow, cg0 + 1);

    float acc[4][4][4];
#pragma unroll
    for (int mi = 0; mi < 4; mi++)
#pragma unroll
        for (int ni = 0; ni < 4; ni++)
#pragma unroll
            for (int q = 0; q < 4; q++) acc[mi][ni][q] = 0.f;

    const int nch = Kp >> 5;

    {
        const size_t ga = (size_t)(m0 + crow) * Kp + cg0 * 8;
        const size_t gb = (size_t)(n0 + crow) * Kp + cg0 * 8;
        CP16(smb + s0,        A + ga); CP16(smb + s1,        A + ga + 8);
        CP16(smb + 8192 + s0, W + gb); CP16(smb + 8192 + s1, W + gb + 8);
        CP_COMMIT();
    }

    for (int ch = 0; ch < nch; ch++) {
        if (ch + 1 < nch) {
            const int k0 = (ch + 1) << 5;
            const size_t ga = (size_t)(m0 + crow) * Kp + k0 + cg0 * 8;
            const size_t gb = (size_t)(n0 + crow) * Kp + k0 + cg0 * 8;
            uint32_t sb = smb + ((ch + 1) & 1) * 16384;
            CP16(sb + s0,        A + ga); CP16(sb + s1,        A + ga + 8);
            CP16(sb + 8192 + s0, W + gb); CP16(sb + 8192 + s1, W + gb + 8);
            CP_COMMIT();
            CP_WAIT1();
        } else {
            CP_WAIT0();
        }
        __syncthreads();

        const uint32_t bA = smb + (ch & 1) * 16384;
        const uint32_t bW = bA + 8192;

#pragma unroll
        for (int ks = 0; ks < 2; ks++) {
            uint32_t ah[4][4], bh[2][4];
#pragma unroll
            for (int mi = 0; mi < 4; mi++) LDSM4(ah[mi], bA + offA[mi][ks]);
#pragma unroll
            for (int p = 0; p < 2; p++)    LDSM4(bh[p], bW + offB[p][ks]);
#pragma unroll
            for (int mi = 0; mi < 4; mi++)
#pragma unroll
                for (int ni = 0; ni < 4; ni++) {
                    uint32_t* bf = &bh[ni >> 1][(ni & 1) * 2];
                    MMA_F16(acc[mi][ni], ah[mi], bf);
                }
        }
        __syncthreads();
    }

    // ---- epilogue: bias + transposed store via smem (two 64-row passes) ----
    float* smf = (float*)dsm;           // 64 x 129 fp32
    const int sbase = m0 >> 5;          // first s of this tile (4 s per tile)
#pragma unroll
    for (int p = 0; p < 2; p++) {
        if (wm == p) {
#pragma unroll
            for (int mi = 0; mi < 4; mi++) {
                const int rl = mi * 16 + (lane >> 2);
#pragma unroll
                for (int ni = 0; ni < 4; ni++) {
                    const int col = wn * 32 + ni * 8 + (lane & 3) * 2;
                    float2 bv = *(const float2*)(bias + n0 + col);
                    smf[rl * 129 + col]           = acc[mi][ni][0] + bv.x;
                    smf[rl * 129 + col + 1]       = acc[mi][ni][1] + bv.y;
                    smf[(rl + 8) * 129 + col]     = acc[mi][ni][2] + bv.x;
                    smf[(rl + 8) * 129 + col + 1] = acc[mi][ni][3] + bv.y;
                }
            }
        }
        __syncthreads();
        // write out: 2 s-values x 128 n; 8 warps x 32 (s,n)-pairs
#pragma unroll
        for (int i = 0; i < 32; i++) {
            int q = wid * 32 + i;
            int sl = q >> 7, n = q & 127;
            int sg = sbase + p * 2 + sl;
            C[((size_t)sg * G4 + n0 + n) * 32 + lane] =
                smf[(sl * 32 + lane) * 129 + n];
        }
        __syncthreads();
    }
}

// =============================================================================
// LSTM scan with HMMA recurrence (R14 proven structure). 512 threads, K split
// across 2 warp groups, single global barrier (atomic + nanosleep).
// hT output now fp16.
// =============================================================================
#define SCAN_SMEM 65536

__global__ __launch_bounds__(512, 1) void lstm_scan_mma(
    const float* __restrict__ xgT, const __half* __restrict__ whh,
    const float* __restrict__ b_hh, __half* __restrict__ hT)
{
    extern __shared__ char dsm[];
    const uint32_t wbase = smem_u32(dsm);          // W: 16 chunks x 2KB
    const uint32_t hbase = wbase + 32768;          // h: 16 chunks x 2KB
    __shared__ float g_s[2][32 * 33 + 16];

    const int tid  = threadIdx.x;
    const int wid  = tid >> 5, lane = tid & 31;
    const int dir  = blockIdx.x >> 6;
    const int blk  = blockIdx.x & 63;
    const int j0   = blk * 8;
    const bool cell = (tid < 256);
    const int b    = tid & 31;
    const int j    = tid >> 5;
    const int jg   = j0 + (cell ? j : 0);

    const int wm = wid & 1, wn = (wid >> 1) & 3, kp = wid >> 3;
    const int sub = lane >> 3, lr = lane & 7;
    uint32_t offA_h[2], offB_h[2];
#pragma unroll
    for (int kh = 0; kh < 2; kh++) {
        offA_h[kh] = swz(wm * 16 + (sub & 1) * 8 + lr, kh * 2 + (sub >> 1));
        offB_h[kh] = swz(wn * 8 + lr,                  kh * 2 + (sub & 1));
    }

    // ---- stage W_hh rows (32 rows x 512 k fp16) once ----
#pragma unroll
    for (int i = 0; i < 4; i++) {
        int gid = i * 512 + tid;
        int r  = gid >> 6;
        int kg = gid & 63;
        int grow = dir * 2048 + (r >> 3) * 512 + j0 + (r & 7);
        CP16(wbase + (kg >> 2) * 2048 + swz(r, kg & 3),
             whh + (size_t)grow * 512 + kg * 8);
    }
    CP_COMMIT();

    // ---- zero h smem (t=0 state) ----
#pragma unroll
    for (int i = 0; i < 4; i++) {
        int gid = i * 512 + tid;
        int r = gid >> 6, kg = gid & 63;
        *(uint4*)(dsm + 32768 + (kg >> 2) * 2048 + swz(r, kg & 3)) =
            make_uint4(0, 0, 0, 0);
    }
    CP_WAIT0();
    __syncthreads();

    const float bh0 = cell ? b_hh[dir * 2048 + 0 * 512 + jg] : 0.f;
    const float bh1 = cell ? b_hh[dir * 2048 + 1 * 512 + jg] : 0.f;
    const float bh2 = cell ? b_hh[dir * 2048 + 2 * 512 + jg] : 0.f;
    const float bh3 = cell ? b_hh[dir * 2048 + 3 * 512 + jg] : 0.f;

    float c = 0.f;
    unsigned ls = 0;

    for (int t = 0; t < Ss; t++) {
        const int s = dir ? (Ss - 1 - t) : t;

        float x0 = 0.f, x1 = 0.f, x2 = 0.f, x3 = 0.f;
        if (cell) {
            const size_t xi = ((size_t)s * G4 + dir * 2048 + jg) * 32 + b;
            x0 = xgT[xi];
            x1 = xgT[xi + 512 * 32];
            x2 = xgT[xi + 1024 * 32];
            x3 = xgT[xi + 1536 * 32];
        }

        if (t > 0) {
            const __half* hsrc = g_hst + (((t - 1) & 1) * 2 + dir) * (Bb * Hh);
#pragma unroll
            for (int i = 0; i < 4; i++) {
                int gid = i * 512 + tid;
                int bb = gid >> 6, kg = gid & 63;
                CP16(hbase + (kg >> 2) * 2048 + swz(bb, kg & 3),
                     hsrc + bb * 512 + kg * 8);
            }
            CP_COMMIT();
            CP_WAIT0();
        }
        __syncthreads();

        float ae[4] = {0.f, 0.f, 0.f, 0.f};
        float ao[4] = {0.f, 0.f, 0.f, 0.f};
        const uint32_t cb0 = kp * 8 * 2048;
#pragma unroll
        for (int ck = 0; ck < 8; ck++) {
            const uint32_t ab = hbase + cb0 + ck * 2048;
            const uint32_t bb = wbase + cb0 + ck * 2048;
            uint32_t a0[4], a1[4], b0[4], b1[4];
            LDSM4(a0, ab + offA_h[0]);
            LDSM2(b0, bb + offB_h[0]);
            LDSM4(a1, ab + offA_h[1]);
            LDSM2(b1, bb + offB_h[1]);
            MMA_F16(ae, a0, b0);
            MMA_F16(ao, a1, b1);
        }

        {
            const int row = wm * 16 + (lane >> 2);
            const int col = wn * 8 + (lane & 3) * 2;
            g_s[kp][row * 33 + col]            = ae[0] + ao[0];
            g_s[kp][row * 33 + col + 1]        = ae[1] + ao[1];
            g_s[kp][(row + 8) * 33 + col]      = ae[2] + ao[2];
            g_s[kp][(row + 8) * 33 + col + 1]  = ae[3] + ao[3];
        }
        __syncthreads();

        if (cell) {
            float gi = g_s[0][b * 33 + j]      + g_s[1][b * 33 + j]      + x0 + bh0;
            float gf = g_s[0][b * 33 + 8 + j]  + g_s[1][b * 33 + 8 + j]  + x1 + bh1;
            float gc = g_s[0][b * 33 + 16 + j] + g_s[1][b * 33 + 16 + j] + x2 + bh2;
            float go = g_s[0][b * 33 + 24 + j] + g_s[1][b * 33 + 24 + j] + x3 + bh3;

            c = sigf(gf) * c + sigf(gi) * tanh_fast(gc);
            float h = sigf(go) * tanh_fast(c);
            __half hh = __float2half(h);

            g_hst[((t & 1) * 2 + dir) * (Bb * Hh) + b * 512 + jg] = hh;
            hT[((size_t)s * 1024 + dir * 512 + jg) * 32 + b] = hh;
        }

        // --- grid barrier (R14 proven: atomic + nanosleep sense-reversal) ---
        __threadfence();
        __syncthreads();
        if (tid == 0) {
            ls ^= 1u;
            unsigned prev = atomicAdd(&g_bar_cnt, 1u);
            if (prev == 127u) {
                atomicExch(&g_bar_cnt, 0u);
                __threadfence();
                g_bar_sense = ls;
            } else {
                while (g_bar_sense != ls) __nanosleep(64);
            }
        }
        __syncthreads();
    }
}

// =============================================================================
// emissions from transposed fp16 h.
// =============================================================================
__global__ __launch_bounds__(256) void emis_t(const __half* __restrict__ hT,
                                              const float* __restrict__ pw,
                                              const float* __restrict__ pb,
                                              float* __restrict__ em)
{
    __shared__ float red[9 * 8 * 32];
    const int s = blockIdx.x, t = threadIdx.x;
    const int kp = t >> 5, b = t & 31;

    float acc[9];
#pragma unroll
    for (int tt = 0; tt < 9; tt++) acc[tt] = 0.f;

    const __half* hp = hT + ((size_t)s * 1024 + kp * 128) * 32 + b;
    const float* pwp = pw + kp * 128;
    for (int k = 0; k < 128; k++) {
        float hv = __half2float(hp[(size_t)k * 32]);
#pragma unroll
        for (int tt = 0; tt < 9; tt++) acc[tt] += hv * pwp[tt * 1024 + k];
    }
#pragma unroll
    for (int tt = 0; tt < 9; tt++) red[(tt * 8 + kp) * 32 + b] = acc[tt];
    __syncthreads();
    if (kp < 4) {
#pragma unroll
        for (int tt = 0; tt < 9; tt++)
            red[(tt * 8 + kp) * 32 + b] += red[(tt * 8 + kp + 4) * 32 + b];
    }
    __syncthreads();
    if (kp < 2) {
#pragma unroll
        for (int tt = 0; tt < 9; tt++)
            red[(tt * 8 + kp) * 32 + b] += red[(tt * 8 + kp + 2) * 32 + b];
    }
    __syncthreads();
    if (kp == 0) {
#pragma unroll
        for (int tt = 0; tt < 9; tt++)
            em[((size_t)(b * 512 + s)) * 9 + tt] =
                red[(tt * 8) * 32 + b] + red[(tt * 8 + 1) * 32 + b] + pb[tt];
    }
}

// =============================================================================
// CRF NLL per batch (warp per batch); target_tag arrives int32.
// =============================================================================
__global__ __launch_bounds__(32) void crf_kernel(const float* __restrict__ em,
                                                 const int* __restrict__ tags,
                                                 const int* __restrict__ mask,
                                                 const float* __restrict__ trans,
                                                 const float* __restrict__ st,
                                                 const float* __restrict__ en,
                                                 float* __restrict__ outp)
{
    const int b = blockIdx.x, lane = threadIdx.x;
    const float* eb = em + (size_t)b * Ss * Tt;
    const int* tb = tags + (size_t)b * Ss;
    const int* mb = mask + (size_t)b * Ss;

    float part = 0.f; int cnt = 0;
    for (int t = 1 + lane; t < Ss; t += 32) {
        float mf = (float)mb[t];
        int tg = tb[t], tp = tb[t - 1];
        part += (eb[t * Tt + tg] + trans[tp * Tt + tg]) * mf;
    }
    for (int t = lane; t < Ss; t += 32) cnt += (mb[t] != 0);
#pragma unroll
    for (int o = 16; o; o >>= 1) {
        part += __shfl_down_sync(0xffffffffu, part, o);
        cnt  += __shfl_down_sync(0xffffffffu, cnt, o);
    }
    cnt  = __shfl_sync(0xffffffffu, cnt, 0);
    part = __shfl_sync(0xffffffffu, part, 0);

    const int jj = lane;
    const bool act = (jj < Tt);
    float trl[9];
#pragma unroll
    for (int i = 0; i < 9; i++) trl[i] = act ? trans[i * Tt + jj] : 0.f;
    float alpha = act ? (st[jj] + eb[jj]) : -1e30f;

    for (int t = 1; t < Ss; t++) {
        float ai[9];
        float m = -1e30f;
#pragma unroll
        for (int i = 0; i < 9; i++) {
            ai[i] = __shfl_sync(0xffffffffu, alpha, i) + trl[i];
            m = fmaxf(m, ai[i]);
        }
        float ssum = 0.f;
#pragma unroll
        for (int i = 0; i < 9; i++) ssum += __expf(ai[i] - m);
        float nxt = m + __logf(ssum) + (act ? eb[t * Tt + jj] : 0.f);
        if (act && mb[t]) alpha = nxt;
    }

    float v = act ? (alpha + en[jj]) : -1e30f;
    float mm = v;
#pragma unroll
    for (int o = 16; o; o >>= 1) mm = fmaxf(mm, __shfl_xor_sync(0xffffffffu, mm, o));
    float ex = __expf(v - mm);
#pragma unroll
    for (int o = 16; o; o >>= 1) ex += __shfl_xor_sync(0xffffffffu, ex, o);
    float denom = mm + __logf(ex);

    if (lane == 0) {
        int t0 = tb[0];
        float num = st[t0] + eb[t0] + part + en[tb[cnt - 1]];
        outp[b] = num - denom;
    }
}

__global__ void final_kernel(const float* __restrict__ p, float* __restrict__ out)
{
    const int lane = threadIdx.x;
    float v = p[lane];
#pragma unroll
    for (int o = 16; o; o >>= 1) v += __shfl_down_sync(0xffffffffu, v, o);
    if (lane == 0) out[0] = -(v / 32.f);
}

// =============================================================================
// kernel_launch
// =============================================================================
extern "C" void kernel_launch(void* const* d_in, const int* in_sizes, int n_in,
                              void* d_out, int out_size)
{
    const float* we   = (const float*)d_in[0];
    const int*   tg   = (const int*)d_in[1];
    const int*   mk   = (const int*)d_in[2];
    const float* wih0 = (const float*)d_in[3];
    const float* whh0 = (const float*)d_in[4];
    const float* bih0 = (const float*)d_in[5];
    const float* bhh0 = (const float*)d_in[6];
    const float* wih1 = (const float*)d_in[7];
    const float* whh1 = (const float*)d_in[8];
    const float* bih1 = (const float*)d_in[9];
    const float* bhh1 = (const float*)d_in[10];
    const float* pw   = (const float*)d_in[11];
    const float* pb   = (const float*)d_in[12];
    const float* tr   = (const float*)d_in[13];
    const float* st   = (const float*)d_in[14];
    const float* en   = (const float*)d_in[15];

    float *xgT, *emis, *part;
    __half *hT, *Af, *Wf, *Whh;
    cudaGetSymbolAddress((void**)&xgT,  g_xgT);
    cudaGetSymbolAddress((void**)&hT,   g_hT);
    cudaGetSymbolAddress((void**)&emis, g_emis);
    cudaGetSymbolAddress((void**)&part, g_part);
    cudaGetSymbolAddress((void**)&Af,   g_Af);
    cudaGetSymbolAddress((void**)&Wf,   g_Wf);
    cudaGetSymbolAddress((void**)&Whh,  g_Whh);

    cudaFuncSetAttribute(lstm_scan_mma, cudaFuncAttributeMaxDynamicSharedMemorySize, SCAN_SMEM);
    cudaFuncSetAttribute(gemm_mma,      cudaFuncAttributeMaxDynamicSharedMemorySize, GEMM_SMEM);

    dim3 ggrid(32, 128);        // GEMM (N/128, M/128)
    dim3 hgrid(8, 512);         // h transpose (k-tiles, s)

    // ---- Layer 0 ----
    conv_weT<<<512, 256>>>(we, Af);                     // A time-major fp16
    conv_f16<<<512, 256>>>(wih0, Wf, G4, Ee, 320);
    gemm_mma<<<ggrid, 256, GEMM_SMEM>>>(Af, Wf, bih0, xgT, 320);   // writes transposed
    conv_f16<<<1024, 256>>>(whh0, Whh, 4096, 512, 512);
    lstm_scan_mma<<<128, 512, SCAN_SMEM>>>(xgT, Whh, bhh0, hT);

    // ---- Layer 1 ----
    transp_hA<<<hgrid, 256>>>(hT, Af);                  // time-major fp16 A
    conv_f16<<<1024, 256>>>(wih1, Wf, G4, 1024, 1024);
    gemm_mma<<<ggrid, 256, GEMM_SMEM>>>(Af, Wf, bih1, xgT, 1024);
    conv_f16<<<1024, 256>>>(whh1, Whh, 4096, 512, 512);
    lstm_scan_mma<<<128, 512, SCAN_SMEM>>>(xgT, Whh, bhh1, hT);

    // ---- Emissions + CRF + final reduce ----
    emis_t<<<512, 256>>>(hT, pw, pb, emis);
    crf_kernel<<<32, 32>>>(emis, tg, mk, tr, st, en, part);
    final_kernel<<<1, 32>>>(part, (float*)d_out);
}

// round 17
// speedup vs baseline: 1.1392x; 1.0535x over previous
#include <cuda_runtime.h>
#include <cuda_fp16.h>
#include <cstdint>
#include <math.h>

// Problem dims
#define Bb 32
#define Ss 512
#define Ee 300
#define Hh 512
#define Tt 9
#define G4 4096                 // 2 dirs * 4H
#define MROWS (Bb*Ss)           // 16384

// ---------------- scratch (device globals; no allocation allowed) ----------------
__device__ __half g_xgT[(size_t)MROWS * G4];    // GEMM out, transposed [(s*4096+n)*32+b] fp16
__device__ __half g_hT [(size_t)MROWS * 1024];  // scan output [(s*1024+k)*32+b] fp16
__device__ float g_emis[(size_t)MROWS * Tt];
__device__ float g_part[Bb];
__device__ unsigned int g_bar_cnt = 0;
__device__ volatile unsigned int g_bar_sense = 0;
// fp16 operand buffers
__device__ __half g_Af[(size_t)MROWS * 1024];   // A operand, time-major rows (s*32+b)
__device__ __half g_Wf[(size_t)G4 * 1024];
__device__ __half g_Whh[(size_t)2 * 2048 * 512];
__device__ __half g_hst[2 * 2 * Bb * Hh];       // fp16 h-state ring [buf][dir][b][k]

// ---------------- helpers ----------------
__device__ __forceinline__ uint32_t smem_u32(const void* p) {
    uint32_t a;
    asm("{ .reg .u64 t; cvta.to.shared.u64 t, %1; cvt.u32.u64 %0, t; }" : "=r"(a) : "l"(p));
    return a;
}
#define CP16(sm, gp) \
    asm volatile("cp.async.cg.shared.global [%0], [%1], 16;" :: "r"(sm), "l"(gp))
#define CP_COMMIT() asm volatile("cp.async.commit_group;" ::: "memory")
#define CP_WAIT1()  asm volatile("cp.async.wait_group 1;" ::: "memory")
#define CP_WAIT0()  asm volatile("cp.async.wait_group 0;" ::: "memory")
#define LDSM4(r, a) \
    asm volatile("ldmatrix.sync.aligned.m8n8.x4.shared.b16 {%0,%1,%2,%3}, [%4];" \
        : "=r"((r)[0]), "=r"((r)[1]), "=r"((r)[2]), "=r"((r)[3]) : "r"(a))
#define LDSM2(r, a) \
    asm volatile("ldmatrix.sync.aligned.m8n8.x2.shared.b16 {%0,%1}, [%2];" \
        : "=r"((r)[0]), "=r"((r)[1]) : "r"(a))
#define MMA_F16(c, a, b) \
    asm volatile("mma.sync.aligned.m16n8k16.row.col.f32.f16.f16.f32 " \
        "{%0,%1,%2,%3}, {%4,%5,%6,%7}, {%8,%9}, {%0,%1,%2,%3};" \
        : "+f"((c)[0]), "+f"((c)[1]), "+f"((c)[2]), "+f"((c)[3]) \
        : "r"((a)[0]), "r"((a)[1]), "r"((a)[2]), "r"((a)[3]), "r"((b)[0]), "r"((b)[1]))

__device__ __forceinline__ float tanh_fast(float x) {
    float r;
    asm("tanh.approx.f32 %0, %1;" : "=f"(r) : "f"(x));
    return r;
}
__device__ __forceinline__ float sigf(float x) { return 1.f / (1.f + __expf(-x)); }

// swizzled smem byte offset for (row, 16B-granule g); 64B rows
__device__ __forceinline__ uint32_t swz(int row, int g) {
    return (uint32_t)(row * 64 + ((g ^ ((row >> 1) & 3)) << 4));
}

// =============================================================================
// fp32 -> fp16 convert (row-major preserved, K padded). For W operands.
// =============================================================================
__global__ __launch_bounds__(256) void conv_f16(const float* __restrict__ in,
                                                __half* __restrict__ out,
                                                int rows, int Kin, int Kp)
{
    int total = rows * Kp;
    for (int idx = blockIdx.x * 256 + threadIdx.x; idx < total; idx += gridDim.x * 256) {
        int r = idx / Kp, c = idx - r * Kp;
        float v = (c < Kin) ? in[(size_t)r * Kin + c] : 0.f;
        out[idx] = __float2half(v);
    }
}

// =============================================================================
// we (B,S,E) -> Af[(s*32+b)*320 + e] fp16 (row permutation + pad). grid = 512 s.
// =============================================================================
__global__ __launch_bounds__(256) void conv_weT(const float* __restrict__ we,
                                                __half* __restrict__ Af)
{
    const int s = blockIdx.x;
    for (int idx = threadIdx.x; idx < 32 * 320; idx += 256) {
        int b = idx / 320, e = idx - b * 320;
        float v = (e < Ee) ? we[((size_t)(b * 512 + s)) * Ee + e] : 0.f;
        Af[((size_t)(s * 32 + b)) * 320 + e] = __float2half(v);
    }
}

// =============================================================================
// hT fp16 [(s*1024+k)*32+b] -> Af[(s*32+b)*1024 + k] fp16 (layer-1 A operand).
// grid (8 k-tiles, 512 s), 256 threads.
// =============================================================================
__global__ __launch_bounds__(256) void transp_hA(const __half* __restrict__ hT,
                                                 __half* __restrict__ Af)
{
    __shared__ __half ts[128 * 33];
    const int s = blockIdx.y, k0 = blockIdx.x * 128, t = threadIdx.x;
#pragma unroll
    for (int i = 0; i < 16; i++) {
        int e = i * 256 + t;
        int bb = e & 31, kk = e >> 5;
        ts[kk * 33 + bb] = hT[((size_t)s * 1024 + k0 + kk) * 32 + bb];
    }
    __syncthreads();
#pragma unroll
    for (int i = 0; i < 16; i++) {
        int f = i * 256 + t;
        int bb = f >> 7, kk = f & 127;
        Af[((size_t)(s * 32 + bb)) * 1024 + k0 + kk] = ts[kk * 33 + bb];
    }
}

// =============================================================================
// GEMM via mma.sync (fp16, fp32 accum), A in time-major rows (s*32+b).
// Writes output DIRECTLY TRANSPOSED as fp16: xgT[(s*4096+n0+n)*32+b].
// Tile 128x128 (= 4 s x 32 b), BK=32, 256 thr. Epilogue: two 64-row passes
// staged through smem (64x129 fp32) for coalesced transposed stores.
// =============================================================================
#define GEMM_SMEM 33024   // max(mainloop 32KB, epilogue 64*129*4)

__global__ __launch_bounds__(256, 2) void gemm_mma(
    const __half* __restrict__ A, const __half* __restrict__ W,
    const float* __restrict__ bias, __half* __restrict__ C, int Kp)
{
    extern __shared__ char dsm[];
    const uint32_t smb = smem_u32(dsm);

    const int tid  = threadIdx.x;
    const int wid  = tid >> 5, lane = tid & 31;
    const int wm   = wid >> 2;
    const int wn   = wid & 3;
    const int m0   = blockIdx.y * 128;
    const int n0   = blockIdx.x * 128;

    const int sub = lane >> 3, lr = lane & 7;
    uint32_t offA[4][2], offB[2][2];
#pragma unroll
    for (int mi = 0; mi < 4; mi++) {
        int mrow = wm * 64 + mi * 16 + (sub & 1) * 8 + lr;
#pragma unroll
        for (int ks = 0; ks < 2; ks++)
            offA[mi][ks] = swz(mrow, ks * 2 + (sub >> 1));
    }
#pragma unroll
    for (int p = 0; p < 2; p++) {
        int nrow = wn * 32 + (p * 2 + (sub >> 1)) * 8 + lr;
#pragma unroll
        for (int ks = 0; ks < 2; ks++)
            offB[p][ks] = swz(nrow, ks * 2 + (sub & 1));
    }

    const int crow = tid >> 1;
    const int cg0  = (tid & 1) * 2;
    const uint32_t s0 = swz(crow, cg0), s1 = swz(crow, cg0 + 1);

    float acc[4][4][4];
#pragma unroll
    for (int mi = 0; mi < 4; mi++)
#pragma unroll
        for (int ni = 0; ni < 4; ni++)
#pragma unroll
            for (int q = 0; q < 4; q++) acc[mi][ni][q] = 0.f;

    const int nch = Kp >> 5;

    {
        const size_t ga = (size_t)(m0 + crow) * Kp + cg0 * 8;
        const size_t gb = (size_t)(n0 + crow) * Kp + cg0 * 8;
        CP16(smb + s0,        A + ga); CP16(smb + s1,        A + ga + 8);
        CP16(smb + 8192 + s0, W + gb); CP16(smb + 8192 + s1, W + gb + 8);
        CP_COMMIT();
    }

    for (int ch = 0; ch < nch; ch++) {
        if (ch + 1 < nch) {
            const int k0 = (ch + 1) << 5;
            const size_t ga = (size_t)(m0 + crow) * Kp + k0 + cg0 * 8;
            const size_t gb = (size_t)(n0 + crow) * Kp + k0 + cg0 * 8;
            uint32_t sb = smb + ((ch + 1) & 1) * 16384;
            CP16(sb + s0,        A + ga); CP16(sb + s1,        A + ga + 8);
            CP16(sb + 8192 + s0, W + gb); CP16(sb + 8192 + s1, W + gb + 8);
            CP_COMMIT();
            CP_WAIT1();
        } else {
            CP_WAIT0();
        }
        __syncthreads();

        const uint32_t bA = smb + (ch & 1) * 16384;
        const uint32_t bW = bA + 8192;

#pragma unroll
        for (int ks = 0; ks < 2; ks++) {
            uint32_t ah[4][4], bh[2][4];
#pragma unroll
            for (int mi = 0; mi < 4; mi++) LDSM4(ah[mi], bA + offA[mi][ks]);
#pragma unroll
            for (int p = 0; p < 2; p++)    LDSM4(bh[p], bW + offB[p][ks]);
#pragma unroll
            for (int mi = 0; mi < 4; mi++)
#pragma unroll
                for (int ni = 0; ni < 4; ni++) {
                    uint32_t* bf = &bh[ni >> 1][(ni & 1) * 2];
                    MMA_F16(acc[mi][ni], ah[mi], bf);
                }
        }
        __syncthreads();
    }

    // ---- epilogue: bias + transposed fp16 store via smem (two 64-row passes) ----
    float* smf = (float*)dsm;           // 64 x 129 fp32
    const int sbase = m0 >> 5;          // first s of this tile (4 s per tile)
#pragma unroll
    for (int p = 0; p < 2; p++) {
        if (wm == p) {
#pragma unroll
            for (int mi = 0; mi < 4; mi++) {
                const int rl = mi * 16 + (lane >> 2);
#pragma unroll
                for (int ni = 0; ni < 4; ni++) {
                    const int col = wn * 32 + ni * 8 + (lane & 3) * 2;
                    float2 bv = *(const float2*)(bias + n0 + col);
                    smf[rl * 129 + col]           = acc[mi][ni][0] + bv.x;
                    smf[rl * 129 + col + 1]       = acc[mi][ni][1] + bv.y;
                    smf[(rl + 8) * 129 + col]     = acc[mi][ni][2] + bv.x;
                    smf[(rl + 8) * 129 + col + 1] = acc[mi][ni][3] + bv.y;
                }
            }
        }
        __syncthreads();
#pragma unroll
        for (int i = 0; i < 32; i++) {
            int q = wid * 32 + i;
            int sl = q >> 7, n = q & 127;
            int sg = sbase + p * 2 + sl;
            C[((size_t)sg * G4 + n0 + n) * 32 + lane] =
                __float2half(smf[(sl * 32 + lane) * 129 + n]);
        }
        __syncthreads();
    }
}

// =============================================================================
// LSTM scan with HMMA recurrence. 512 threads, K split across 2 warp groups,
// global barrier = atomic arrive + pure-spin sense (1 poller/block), and a
// SINGLE-thread gpu fence (PTX cumulativity via bar.sync) before arrival.
// =============================================================================
#define SCAN_SMEM 65536

__global__ __launch_bounds__(512, 1) void lstm_scan_mma(
    const __half* __restrict__ xgT, const __half* __restrict__ whh,
    const float* __restrict__ b_hh, __half* __restrict__ hT)
{
    extern __shared__ char dsm[];
    const uint32_t wbase = smem_u32(dsm);          // W: 16 chunks x 2KB
    const uint32_t hbase = wbase + 32768;          // h: 16 chunks x 2KB
    __shared__ float g_s[2][32 * 33 + 16];

    const int tid  = threadIdx.x;
    const int wid  = tid >> 5, lane = tid & 31;
    const int dir  = blockIdx.x >> 6;
    const int blk  = blockIdx.x & 63;
    const int j0   = blk * 8;
    const bool cell = (tid < 256);
    const int b    = tid & 31;
    const int j    = tid >> 5;
    const int jg   = j0 + (cell ? j : 0);

    const int wm = wid & 1, wn = (wid >> 1) & 3, kp = wid >> 3;
    const int sub = lane >> 3, lr = lane & 7;
    uint32_t offA_h[2], offB_h[2];
#pragma unroll
    for (int kh = 0; kh < 2; kh++) {
        offA_h[kh] = swz(wm * 16 + (sub & 1) * 8 + lr, kh * 2 + (sub >> 1));
        offB_h[kh] = swz(wn * 8 + lr,                  kh * 2 + (sub & 1));
    }

    // ---- stage W_hh rows (32 rows x 512 k fp16) once ----
#pragma unroll
    for (int i = 0; i < 4; i++) {
        int gid = i * 512 + tid;
        int r  = gid >> 6;
        int kg = gid & 63;
        int grow = dir * 2048 + (r >> 3) * 512 + j0 + (r & 7);
        CP16(wbase + (kg >> 2) * 2048 + swz(r, kg & 3),
             whh + (size_t)grow * 512 + kg * 8);
    }
    CP_COMMIT();

    // ---- zero h smem (t=0 state) ----
#pragma unroll
    for (int i = 0; i < 4; i++) {
        int gid = i * 512 + tid;
        int r = gid >> 6, kg = gid & 63;
        *(uint4*)(dsm + 32768 + (kg >> 2) * 2048 + swz(r, kg & 3)) =
            make_uint4(0, 0, 0, 0);
    }
    CP_WAIT0();
    __syncthreads();

    const float bh0 = cell ? b_hh[dir * 2048 + 0 * 512 + jg] : 0.f;
    const float bh1 = cell ? b_hh[dir * 2048 + 1 * 512 + jg] : 0.f;
    const float bh2 = cell ? b_hh[dir * 2048 + 2 * 512 + jg] : 0.f;
    const float bh3 = cell ? b_hh[dir * 2048 + 3 * 512 + jg] : 0.f;

    float c = 0.f;
    unsigned ls = 0;

    for (int t = 0; t < Ss; t++) {
        const int s = dir ? (Ss - 1 - t) : t;

        float x0 = 0.f, x1 = 0.f, x2 = 0.f, x3 = 0.f;
        if (cell) {
            const size_t xi = ((size_t)s * G4 + dir * 2048 + jg) * 32 + b;
            x0 = __half2float(xgT[xi]);
            x1 = __half2float(xgT[xi + 512 * 32]);
            x2 = __half2float(xgT[xi + 1024 * 32]);
            x3 = __half2float(xgT[xi + 1536 * 32]);
        }

        if (t > 0) {
            const __half* hsrc = g_hst + (((t - 1) & 1) * 2 + dir) * (Bb * Hh);
#pragma unroll
            for (int i = 0; i < 4; i++) {
                int gid = i * 512 + tid;
                int bb = gid >> 6, kg = gid & 63;
                CP16(hbase + (kg >> 2) * 2048 + swz(bb, kg & 3),
                     hsrc + bb * 512 + kg * 8);
            }
            CP_COMMIT();
            CP_WAIT0();
        }
        __syncthreads();

        float ae[4] = {0.f, 0.f, 0.f, 0.f};
        float ao[4] = {0.f, 0.f, 0.f, 0.f};
        const uint32_t cb0 = kp * 8 * 2048;
#pragma unroll
        for (int ck = 0; ck < 8; ck++) {
            const uint32_t ab = hbase + cb0 + ck * 2048;
            const uint32_t bb = wbase + cb0 + ck * 2048;
            uint32_t a0[4], a1[4], b0[4], b1[4];
            LDSM4(a0, ab + offA_h[0]);
            LDSM2(b0, bb + offB_h[0]);
            LDSM4(a1, ab + offA_h[1]);
            LDSM2(b1, bb + offB_h[1]);
            MMA_F16(ae, a0, b0);
            MMA_F16(ao, a1, b1);
        }

        {
            const int row = wm * 16 + (lane >> 2);
            const int col = wn * 8 + (lane & 3) * 2;
            g_s[kp][row * 33 + col]            = ae[0] + ao[0];
            g_s[kp][row * 33 + col + 1]        = ae[1] + ao[1];
            g_s[kp][(row + 8) * 33 + col]      = ae[2] + ao[2];
            g_s[kp][(row + 8) * 33 + col + 1]  = ae[3] + ao[3];
        }
        __syncthreads();

        if (cell) {
            float gi = g_s[0][b * 33 + j]      + g_s[1][b * 33 + j]      + x0 + bh0;
            float gf = g_s[0][b * 33 + 8 + j]  + g_s[1][b * 33 + 8 + j]  + x1 + bh1;
            float gc = g_s[0][b * 33 + 16 + j] + g_s[1][b * 33 + 16 + j] + x2 + bh2;
            float go = g_s[0][b * 33 + 24 + j] + g_s[1][b * 33 + 24 + j] + x3 + bh3;

            c = sigf(gf) * c + sigf(gi) * tanh_fast(gc);
            float h = sigf(go) * tanh_fast(c);
            __half hh = __float2half(h);

            g_hst[((t & 1) * 2 + dir) * (Bb * Hh) + b * 512 + jg] = hh;
            hT[((size_t)s * 1024 + dir * 512 + jg) * 32 + b] = hh;
        }

        // --- grid barrier: bar.sync, then ONE thread fences + arrives;
        //     release observed by pure spin (128 pollers total). ---
        __syncthreads();
        if (tid == 0) {
            __threadfence();    // cumulativity: publishes all CTA stores
            ls ^= 1u;
            unsigned prev = atomicAdd(&g_bar_cnt, 1u);
            if (prev == 127u) {
                atomicExch(&g_bar_cnt, 0u);
                __threadfence();
                g_bar_sense = ls;
            } else {
                while (g_bar_sense != ls) {}
            }
        }
        __syncthreads();
    }
}

// =============================================================================
// emissions from transposed fp16 h.
// =============================================================================
__global__ __launch_bounds__(256) void emis_t(const __half* __restrict__ hT,
                                              const float* __restrict__ pw,
                                              const float* __restrict__ pb,
                                              float* __restrict__ em)
{
    __shared__ float red[9 * 8 * 32];
    const int s = blockIdx.x, t = threadIdx.x;
    const int kp = t >> 5, b = t & 31;

    float acc[9];
#pragma unroll
    for (int tt = 0; tt < 9; tt++) acc[tt] = 0.f;

    const __half* hp = hT + ((size_t)s * 1024 + kp * 128) * 32 + b;
    const float* pwp = pw + kp * 128;
    for (int k = 0; k < 128; k++) {
        float hv = __half2float(hp[(size_t)k * 32]);
#pragma unroll
        for (int tt = 0; tt < 9; tt++) acc[tt] += hv * pwp[tt * 1024 + k];
    }
#pragma unroll
    for (int tt = 0; tt < 9; tt++) red[(tt * 8 + kp) * 32 + b] = acc[tt];
    __syncthreads();
    if (kp < 4) {
#pragma unroll
        for (int tt = 0; tt < 9; tt++)
            red[(tt * 8 + kp) * 32 + b] += red[(tt * 8 + kp + 4) * 32 + b];
    }
    __syncthreads();
    if (kp < 2) {
#pragma unroll
        for (int tt = 0; tt < 9; tt++)
            red[(tt * 8 + kp) * 32 + b] += red[(tt * 8 + kp + 2) * 32 + b];
    }
    __syncthreads();
    if (kp == 0) {
#pragma unroll
        for (int tt = 0; tt < 9; tt++)
            em[((size_t)(b * 512 + s)) * 9 + tt] =
                red[(tt * 8) * 32 + b] + red[(tt * 8 + 1) * 32 + b] + pb[tt];
    }
}

// =============================================================================
// CRF NLL per batch (warp per batch); target_tag arrives int32.
// =============================================================================
__global__ __launch_bounds__(32) void crf_kernel(const float* __restrict__ em,
                                                 const int* __restrict__ tags,
                                                 const int* __restrict__ mask,
                                                 const float* __restrict__ trans,
                                                 const float* __restrict__ st,
                                                 const float* __restrict__ en,
                                                 float* __restrict__ outp)
{
    const int b = blockIdx.x, lane = threadIdx.x;
    const float* eb = em + (size_t)b * Ss * Tt;
    const int* tb = tags + (size_t)b * Ss;
    const int* mb = mask + (size_t)b * Ss;

    float part = 0.f; int cnt = 0;
    for (int t = 1 + lane; t < Ss; t += 32) {
        float mf = (float)mb[t];
        int tg = tb[t], tp = tb[t - 1];
        part += (eb[t * Tt + tg] + trans[tp * Tt + tg]) * mf;
    }
    for (int t = lane; t < Ss; t += 32) cnt += (mb[t] != 0);
#pragma unroll
    for (int o = 16; o; o >>= 1) {
        part += __shfl_down_sync(0xffffffffu, part, o);
        cnt  += __shfl_down_sync(0xffffffffu, cnt, o);
    }
    cnt  = __shfl_sync(0xffffffffu, cnt, 0);
    part = __shfl_sync(0xffffffffu, part, 0);

    const int jj = lane;
    const bool act = (jj < Tt);
    float trl[9];
#pragma unroll
    for (int i = 0; i < 9; i++) trl[i] = act ? trans[i * Tt + jj] : 0.f;
    float alpha = act ? (st[jj] + eb[jj]) : -1e30f;

    for (int t = 1; t < Ss; t++) {
        float ai[9];
        float m = -1e30f;
#pragma unroll
        for (int i = 0; i < 9; i++) {
            ai[i] = __shfl_sync(0xffffffffu, alpha, i) + trl[i];
            m = fmaxf(m, ai[i]);
        }
        float ssum = 0.f;
#pragma unroll
        for (int i = 0; i < 9; i++) ssum += __expf(ai[i] - m);
        float nxt = m + __logf(ssum) + (act ? eb[t * Tt + jj] : 0.f);
        if (act && mb[t]) alpha = nxt;
    }

    float v = act ? (alpha + en[jj]) : -1e30f;
    float mm = v;
#pragma unroll
    for (int o = 16; o; o >>= 1) mm = fmaxf(mm, __shfl_xor_sync(0xffffffffu, mm, o));
    float ex = __expf(v - mm);
#pragma unroll
    for (int o = 16; o; o >>= 1) ex += __shfl_xor_sync(0xffffffffu, ex, o);
    float denom = mm + __logf(ex);

    if (lane == 0) {
        int t0 = tb[0];
        float num = st[t0] + eb[t0] + part + en[tb[cnt - 1]];
        outp[b] = num - denom;
    }
}

__global__ void final_kernel(const float* __restrict__ p, float* __restrict__ out)
{
    const int lane = threadIdx.x;
    float v = p[lane];
#pragma unroll
    for (int o = 16; o; o >>= 1) v += __shfl_down_sync(0xffffffffu, v, o);
    if (lane == 0) out[0] = -(v / 32.f);
}

// =============================================================================
// kernel_launch
// =============================================================================
extern "C" void kernel_launch(void* const* d_in, const int* in_sizes, int n_in,
                              void* d_out, int out_size)
{
    const float* we   = (const float*)d_in[0];
    const int*   tg   = (const int*)d_in[1];
    const int*   mk   = (const int*)d_in[2];
    const float* wih0 = (const float*)d_in[3];
    const float* whh0 = (const float*)d_in[4];
    const float* bih0 = (const float*)d_in[5];
    const float* bhh0 = (const float*)d_in[6];
    const float* wih1 = (const float*)d_in[7];
    const float* whh1 = (const float*)d_in[8];
    const float* bih1 = (const float*)d_in[9];
    const float* bhh1 = (const float*)d_in[10];
    const float* pw   = (const float*)d_in[11];
    const float* pb   = (const float*)d_in[12];
    const float* tr   = (const float*)d_in[13];
    const float* st   = (const float*)d_in[14];
    const float* en   = (const float*)d_in[15];

    float *emis, *part;
    __half *xgT, *hT, *Af, *Wf, *Whh;
    cudaGetSymbolAddress((void**)&xgT,  g_xgT);
    cudaGetSymbolAddress((void**)&hT,   g_hT);
    cudaGetSymbolAddress((void**)&emis, g_emis);
    cudaGetSymbolAddress((void**)&part, g_part);
    cudaGetSymbolAddress((void**)&Af,   g_Af);
    cudaGetSymbolAddress((void**)&Wf,   g_Wf);
    cudaGetSymbolAddress((void**)&Whh,  g_Whh);

    cudaFuncSetAttribute(lstm_scan_mma, cudaFuncAttributeMaxDynamicSharedMemorySize, SCAN_SMEM);
    cudaFuncSetAttribute(gemm_mma,      cudaFuncAttributeMaxDynamicSharedMemorySize, GEMM_SMEM);

    dim3 ggrid(32, 128);        // GEMM (N/128, M/128)
    dim3 hgrid(8, 512);         // h transpose (k-tiles, s)

    // ---- Layer 0 ----
    conv_weT<<<512, 256>>>(we, Af);                     // A time-major fp16
    conv_f16<<<512, 256>>>(wih0, Wf, G4, Ee, 320);
    gemm_mma<<<ggrid, 256, GEMM_SMEM>>>(Af, Wf, bih0, xgT, 320);   // writes transposed fp16
    conv_f16<<<1024, 256>>>(whh0, Whh, 4096, 512, 512);
    lstm_scan_mma<<<128, 512, SCAN_SMEM>>>(xgT, Whh, bhh0, hT);

    // ---- Layer 1 ----
    transp_hA<<<hgrid, 256>>>(hT, Af);                  // time-major fp16 A
    conv_f16<<<1024, 256>>>(wih1, Wf, G4, 1024, 1024);
    gemm_mma<<<ggrid, 256, GEMM_SMEM>>>(Af, Wf, bih1, xgT, 1024);
    conv_f16<<<1024, 256>>>(whh1, Whh, 4096, 512, 512);
    lstm_scan_mma<<<128, 512, SCAN_SMEM>>>(xgT, Whh, bhh1, hT);

    // ---- Emissions + CRF + final reduce ----
    emis_t<<<512, 256>>>(hT, pw, pb, emis);
    crf_kernel<<<32, 32>>>(emis, tg, mk, tr, st, en, part);
    final_kernel<<<1, 32>>>(part, (float*)d_out);
}